// round 3
// baseline (speedup 1.0000x reference)
#include <cuda_runtime.h>

// Problem constants
#define SN 4096
#define HN 1024
#define BN 4
#define RN 16
#define NT 33          // 16 wc + 16 we + 1 besum
#define KQ 4           // split-K factor for k1
#define KS (HN / KQ)   // 256 k per split
#define ROWS_TOT (BN * SN)   // 16384

// ---------------- scratch (device globals; no allocation) ----------------
__device__ float g_part[NT * KQ * ROWS_TOT];   // k1 partial sums [n][kq][row]
__device__ float g_Pf[BN * RN * SN];           // scaled cause scores [b][r][s]
__device__ float g_Ut[BN * RN * SN];           // effect dot [b][r][t]
__device__ float g_V[BN * SN];                 // bias-term dot [b][t]

// packed f32x2 FMA (SASS FFMA2) — 2x fp32 FMA throughput
__device__ __forceinline__ float2 ffma2(float2 a, float2 b, float2 c) {
    float2 d;
    asm("fma.rn.f32x2 %0, %1, %2, %3;"
        : "=l"(*reinterpret_cast<unsigned long long*>(&d))
        : "l"(*reinterpret_cast<unsigned long long*>(&a)),
          "l"(*reinterpret_cast<unsigned long long*>(&b)),
          "l"(*reinterpret_cast<unsigned long long*>(&c)));
    return d;
}

// =======================================================================
// k1_partial: per-thread row dot products against all 33 weight rows.
//   grid (64, KQ), block 256. Thread owns row = bx*256+tid, k-slice kq.
//   W slice in smem, read via warp-uniform (broadcast) LDS.128.
// =======================================================================
#define W_PITCH 260    // floats; 260*4=1040 B, 16B-aligned rows

__global__ __launch_bounds__(256, 2)
void k1_partial(const float* __restrict__ hs,
                const float* __restrict__ wc,
                const float* __restrict__ we,
                const float* __restrict__ be) {
    __shared__ __align__(16) float Ws[NT * W_PITCH];

    const int tid = threadIdx.x;
    const int kq = blockIdx.y;
    const int k0 = kq * KS;

    // stage W rows 0..31 (wc|we): 32*256 floats = 2048 float4, 8 per thread
    #pragma unroll
    for (int i = 0; i < 8; i++) {
        int idx = tid + 256 * i;          // 0..2047
        int n = idx >> 6;                 // 64 float4 per row
        int c4 = idx & 63;
        const float* src = (n < 16)
            ? &wc[n * HN + k0 + c4 * 4]
            : &we[(n - 16) * HN + k0 + c4 * 4];
        *reinterpret_cast<float4*>(&Ws[n * W_PITCH + c4 * 4]) =
            *reinterpret_cast<const float4*>(src);
    }
    // row 32 = besum slice (one col per thread, coalesced per r)
    {
        float s = 0.f;
        #pragma unroll
        for (int r = 0; r < RN; r++) s += be[r * HN + k0 + tid];
        Ws[32 * W_PITCH + tid] = s;
    }
    __syncthreads();

    const int row = blockIdx.x * 256 + tid;
    const float4* hrow = reinterpret_cast<const float4*>(
        hs + (size_t)row * HN + k0);

    float2 acc[NT];
    #pragma unroll
    for (int n = 0; n < NT; n++) acc[n] = make_float2(0.f, 0.f);

    #pragma unroll 2
    for (int j = 0; j < KS / 4; j++) {
        float4 h4 = hrow[j];
        float2 hlo = make_float2(h4.x, h4.y);
        float2 hhi = make_float2(h4.z, h4.w);
        #pragma unroll
        for (int n = 0; n < NT; n++) {
            float4 w4 = *reinterpret_cast<const float4*>(&Ws[n * W_PITCH + j * 4]);
            acc[n] = ffma2(hlo, make_float2(w4.x, w4.y), acc[n]);
            acc[n] = ffma2(hhi, make_float2(w4.z, w4.w), acc[n]);
        }
    }

    #pragma unroll
    for (int n = 0; n < NT; n++)
        g_part[(n * KQ + kq) * ROWS_TOT + row] = acc[n].x + acc[n].y;
}

// =======================================================================
// k1_reduce: sum KQ partials, apply epilogue, scatter to P/Ut/V layouts.
//   grid (64, NT), block 256. Fully coalesced.
// =======================================================================
__global__ __launch_bounds__(256)
void k1_reduce(const float* __restrict__ bc,
               const float* __restrict__ strength) {
    const int row = blockIdx.x * 256 + threadIdx.x;
    const int n = blockIdx.y;
    const float* p = &g_part[n * KQ * ROWS_TOT + row];
    float v = p[0] + p[ROWS_TOT] + p[2 * ROWS_TOT] + p[3 * ROWS_TOT];
    const int b = row >> 12;
    const int s = row & (SN - 1);
    if (n < 16)      g_Pf[(b * RN + n) * SN + s] = (v + bc[n]) * strength[n];
    else if (n < 32) g_Ut[(b * RN + (n - 16)) * SN + s] = v;
    else             g_V[b * SN + s] = v;
}

// =======================================================================
// k2_outer: bias[b,s,t] = sum_r P[b,r,s]*U[b,r,t] + V[b,t]
//   No smem, no barriers. 256 thr = 64 t-quads x 4 s-groups (4 s each).
//   P s-paired in regs, U via direct LDG.128 (L1 reuse across y-groups),
//   register transpose -> coalesced float4 stores.
// =======================================================================
__global__ __launch_bounds__(256, 2)
void k2_outer(float* __restrict__ out) {
    const int tid = threadIdx.x;
    const int x = tid & 63;          // t quad lane
    const int y = tid >> 6;          // s group 0..3
    const int b = blockIdx.z;
    const int sB = blockIdx.y * 16 + y * 4;
    const int tQ = blockIdx.x * 1024;

    // P: 2 s-pairs x 16 r (64 regs), broadcast LDG.128 per r
    float2 pp[2][RN];
    #pragma unroll
    for (int r = 0; r < RN; r++) {
        float4 p4 = *reinterpret_cast<const float4*>(&g_Pf[(b * RN + r) * SN + sB]);
        pp[0][r] = make_float2(p4.x, p4.y);
        pp[1][r] = make_float2(p4.z, p4.w);
    }

    const float* uB = &g_Ut[b * RN * SN];

    #pragma unroll
    for (int it = 0; it < 4; it++) {
        const int tBase = tQ + it * 256;

        float4 v4 = *reinterpret_cast<const float4*>(&g_V[b * SN + tBase + 4 * x]);
        float2 acc[2][4];
        #pragma unroll
        for (int sp = 0; sp < 2; sp++) {
            acc[sp][0] = make_float2(v4.x, v4.x);
            acc[sp][1] = make_float2(v4.y, v4.y);
            acc[sp][2] = make_float2(v4.z, v4.z);
            acc[sp][3] = make_float2(v4.w, v4.w);
        }

        #pragma unroll
        for (int r = 0; r < RN; r++) {
            float4 u4 = *reinterpret_cast<const float4*>(
                &uB[r * SN + tBase + 4 * x]);
            float2 d0 = make_float2(u4.x, u4.x);
            float2 d1 = make_float2(u4.y, u4.y);
            float2 d2 = make_float2(u4.z, u4.z);
            float2 d3 = make_float2(u4.w, u4.w);
            #pragma unroll
            for (int sp = 0; sp < 2; sp++) {
                acc[sp][0] = ffma2(pp[sp][r], d0, acc[sp][0]);
                acc[sp][1] = ffma2(pp[sp][r], d1, acc[sp][1]);
                acc[sp][2] = ffma2(pp[sp][r], d2, acc[sp][2]);
                acc[sp][3] = ffma2(pp[sp][r], d3, acc[sp][3]);
            }
        }

        // register transpose: s-pairs -> per-s float4 rows, coalesced stores
        #pragma unroll
        for (int sp = 0; sp < 2; sp++) {
            float* o0 = &out[(size_t)(b * SN + sB + 2 * sp) * SN + tBase];
            float* o1 = &out[(size_t)(b * SN + sB + 2 * sp + 1) * SN + tBase];
            *reinterpret_cast<float4*>(&o0[4 * x]) =
                make_float4(acc[sp][0].x, acc[sp][1].x, acc[sp][2].x, acc[sp][3].x);
            *reinterpret_cast<float4*>(&o1[4 * x]) =
                make_float4(acc[sp][0].y, acc[sp][1].y, acc[sp][2].y, acc[sp][3].y);
        }
    }
}

// ---------------- launch ----------------
extern "C" void kernel_launch(void* const* d_in, const int* in_sizes, int n_in,
                              void* d_out, int out_size) {
    const float* hs       = (const float*)d_in[0];
    const float* wc       = (const float*)d_in[1];
    const float* bc       = (const float*)d_in[2];
    const float* we       = (const float*)d_in[3];
    const float* be       = (const float*)d_in[4];
    const float* strength = (const float*)d_in[5];
    float* out = (float*)d_out;

    k1_partial<<<dim3(ROWS_TOT / 256, KQ), 256>>>(hs, wc, we, be);
    k1_reduce<<<dim3(ROWS_TOT / 256, NT), 256>>>(bc, strength);
    k2_outer<<<dim3(4, SN / 16, BN), 256>>>(out);
}

// round 4
// speedup vs baseline: 2.3615x; 2.3615x over previous
#include <cuda_runtime.h>

// Problem constants
#define SN 4096
#define HN 1024
#define BN 4
#define RN 16

// ---------------- scratch (device globals; no allocation) ----------------
__device__ float2 g_Pd[BN * SN * RN];     // scaled cause scores, duplicated {p,p}, [b][s][r]
__device__ float  g_Ut[BN * RN * SN];     // effect dot [b][r][t]
__device__ float  g_V[BN * SN];           // bias-term dot [b][t]

// packed f32x2 FMA (SASS FFMA2)
__device__ __forceinline__ float2 ffma2(float2 a, float2 b, float2 c) {
    float2 d;
    asm("fma.rn.f32x2 %0, %1, %2, %3;"
        : "=l"(*reinterpret_cast<unsigned long long*>(&d))
        : "l"(*reinterpret_cast<unsigned long long*>(&a)),
          "l"(*reinterpret_cast<unsigned long long*>(&b)),
          "l"(*reinterpret_cast<unsigned long long*>(&c)));
    return d;
}

__device__ __forceinline__ void cp16(void* smem_dst, const void* gmem_src) {
    unsigned sdst = (unsigned)__cvta_generic_to_shared(smem_dst);
    asm volatile("cp.async.cg.shared.global [%0], [%1], 16;"
                 :: "r"(sdst), "l"(gmem_src) : "memory");
}
__device__ __forceinline__ void cp_commit() {
    asm volatile("cp.async.commit_group;" ::: "memory");
}
__device__ __forceinline__ void cp_wait0() {
    asm volatile("cp.async.wait_group 0;" ::: "memory");
}

// =======================================================================
// kernel 1: [16384 x 1024] @ [1024 x 33] projection (wc | we | sum_be)
//   BM=128, thread tile m=4 x n=5 -> 2.6 B crossbar / lane-FFMA2.
// =======================================================================
#define K1_BM 128
#define K1_KC 32
#define K1_PITCH 36

__global__ __launch_bounds__(256, 1)
void k1_proj(const float* __restrict__ hs,
             const float* __restrict__ wc,
             const float* __restrict__ bc,
             const float* __restrict__ we,
             const float* __restrict__ be,
             const float* __restrict__ strength) {
    __shared__ float besum_s[HN];
    __shared__ __align__(16) float As[2][K1_BM * K1_PITCH];
    __shared__ __align__(16) float Ws[2][40 * K1_PITCH];

    const int tid = threadIdx.x;
    const int x = tid & 31;          // row lane
    const int y = tid >> 5;          // n-group (0..7), 5 outputs each
    const int rowBase = blockIdx.x * K1_BM;

    // zero Ws (rows 33-39 stay zero)
    for (int i = tid; i < 2 * 40 * K1_PITCH; i += 256)
        (&Ws[0][0])[i] = 0.f;

    // per-CTA redundant besum (4 cols per thread, coalesced)
    #pragma unroll
    for (int j = 0; j < 4; j++) {
        int col = tid + 256 * j;
        float s = 0.f;
        #pragma unroll
        for (int r = 0; r < RN; r++) s += be[r * HN + col];
        besum_s[col] = s;
    }
    __syncthreads();

    auto stage = [&](int c, int buf) {
        // A tile: 128 rows x 32 k = 1024 float4, 4 per thread
        #pragma unroll
        for (int i = 0; i < 4; i++) {
            int idx = tid + 256 * i;
            int row = idx >> 3, k4 = idx & 7;
            cp16(&As[buf][row * K1_PITCH + k4 * 4],
                 &hs[(size_t)(rowBase + row) * HN + c * K1_KC + k4 * 4]);
        }
        // W rows 0..31: 256 float4, 1 per thread
        {
            int n = tid >> 3, k4 = tid & 7;
            const float* src = (n < 16)
                ? &wc[n * HN + c * K1_KC + k4 * 4]
                : &we[(n - 16) * HN + c * K1_KC + k4 * 4];
            cp16(&Ws[buf][n * K1_PITCH + k4 * 4], src);
        }
        cp_commit();
        // W row 32 = besum slice
        if (tid < 32)
            Ws[buf][32 * K1_PITCH + tid] = besum_s[c * K1_KC + tid];
    };

    float2 acc[4][5];
    #pragma unroll
    for (int m = 0; m < 4; m++)
        #pragma unroll
        for (int nn = 0; nn < 5; nn++) acc[m][nn] = make_float2(0.f, 0.f);

    stage(0, 0);

    for (int c = 0; c < HN / K1_KC; c++) {
        cp_wait0();
        __syncthreads();
        if (c + 1 < HN / K1_KC) stage(c + 1, (c + 1) & 1);
        const int buf = c & 1;

        #pragma unroll
        for (int kp = 0; kp < K1_KC / 2; kp++) {
            float2 a2[4], b2[5];
            #pragma unroll
            for (int m = 0; m < 4; m++)
                a2[m] = *reinterpret_cast<const float2*>(
                    &As[buf][(x + 32 * m) * K1_PITCH + 2 * kp]);
            #pragma unroll
            for (int nn = 0; nn < 5; nn++)
                b2[nn] = *reinterpret_cast<const float2*>(
                    &Ws[buf][(y * 5 + nn) * K1_PITCH + 2 * kp]);
            #pragma unroll
            for (int m = 0; m < 4; m++)
                #pragma unroll
                for (int nn = 0; nn < 5; nn++)
                    acc[m][nn] = ffma2(a2[m], b2[nn], acc[m][nn]);
        }
        __syncthreads();
    }

    // epilogue
    #pragma unroll
    for (int m = 0; m < 4; m++) {
        int row = rowBase + x + 32 * m;
        int b = row >> 12;
        int s = row & (SN - 1);
        #pragma unroll
        for (int nn = 0; nn < 5; nn++) {
            int n = y * 5 + nn;
            float val = acc[m][nn].x + acc[m][nn].y;
            if (n < 16) {
                float p = (val + bc[n]) * strength[n];
                g_Pd[(b * SN + s) * RN + n] = make_float2(p, p);
            } else if (n < 32) {
                g_Ut[(b * RN + (n - 16)) * SN + s] = val;
            } else if (n == 32) {
                g_V[b * SN + s] = val;
            }
        }
    }
}

// =======================================================================
// kernel 2: bias[b,s,t] = sum_r P[b,s,r]*U[b,r,t] + V[b,t]
//   Thread owns 4 t; U[16] held in registers (float4 each), loaded once.
//   P duplicated {p,p} staged in smem (8KB), read via uniform LDS.128.
//   Per s-step: 8 uniform LDS + 32 FFMA2 + 1 STG.128. wf:fma ~0.75.
// =======================================================================
#define K2_TB 1024     // t per CTA (8 warps x 128)
#define K2_SB 64       // s per CTA

__global__ __launch_bounds__(256, 2)
void k2_outer(float* __restrict__ out) {
    __shared__ __align__(16) float4 Ps[K2_SB * 8];   // 64 s x 16 float2 dup = 8KB

    const int tid = threadIdx.x;
    const int w = tid >> 5;
    const int l = tid & 31;
    const int b = blockIdx.z;
    const int sB = blockIdx.y * K2_SB;
    const int t = blockIdx.x * K2_TB + w * 128 + l * 4;

    // stage P tile (coalesced, 2 float4 per thread)
    const float4* psrc = reinterpret_cast<const float4*>(&g_Pd[(b * SN + sB) * RN]);
    Ps[tid] = psrc[tid];
    Ps[tid + 256] = psrc[tid + 256];

    // U in registers: 16 x float4 (per-warp coalesced 512B loads)
    float4 u[RN];
    #pragma unroll
    for (int r = 0; r < RN; r++)
        u[r] = *reinterpret_cast<const float4*>(&g_Ut[(b * RN + r) * SN + t]);

    float4 vv = *reinterpret_cast<const float4*>(&g_V[b * SN + t]);
    const float2 va = make_float2(vv.x, vv.y);
    const float2 vb = make_float2(vv.z, vv.w);

    __syncthreads();

    float* orow = out + (size_t)(b * SN + sB) * SN + t;

    #pragma unroll 2
    for (int si = 0; si < K2_SB; si++) {
        float4 pq[8];
        #pragma unroll
        for (int j = 0; j < 8; j++) pq[j] = Ps[si * 8 + j];   // uniform LDS.128

        float2 a = va, c2 = vb;
        #pragma unroll
        for (int r = 0; r < RN; r++) {
            float2 p = (r & 1) ? make_float2(pq[r >> 1].z, pq[r >> 1].w)
                               : make_float2(pq[r >> 1].x, pq[r >> 1].y);
            a  = ffma2(p, make_float2(u[r].x, u[r].y), a);
            c2 = ffma2(p, make_float2(u[r].z, u[r].w), c2);
        }

        *reinterpret_cast<float4*>(orow + (size_t)si * SN) =
            make_float4(a.x, a.y, c2.x, c2.y);
    }
}

// ---------------- launch ----------------
extern "C" void kernel_launch(void* const* d_in, const int* in_sizes, int n_in,
                              void* d_out, int out_size) {
    const float* hs       = (const float*)d_in[0];
    const float* wc       = (const float*)d_in[1];
    const float* bc       = (const float*)d_in[2];
    const float* we       = (const float*)d_in[3];
    const float* be       = (const float*)d_in[4];
    const float* strength = (const float*)d_in[5];
    float* out = (float*)d_out;

    k1_proj<<<(BN * SN) / K1_BM, 256>>>(hs, wc, bc, we, be, strength);
    k2_outer<<<dim3(SN / K2_TB, SN / K2_SB, BN), 256>>>(out);
}

// round 5
// speedup vs baseline: 2.4128x; 1.0217x over previous
#include <cuda_runtime.h>

// Problem constants
#define SN 4096
#define HN 1024
#define BN 4
#define RN 16

// ---------------- scratch (device globals; no allocation) ----------------
__device__ float2 g_Pd[BN * SN * RN];     // scaled cause scores, duplicated {p,p}, [b][s][r]
__device__ float  g_Ut[BN * RN * SN];     // effect dot [b][r][t]
__device__ float  g_V[BN * SN];           // bias-term dot [b][t]

// packed f32x2 FMA (SASS FFMA2)
__device__ __forceinline__ float2 ffma2(float2 a, float2 b, float2 c) {
    float2 d;
    asm("fma.rn.f32x2 %0, %1, %2, %3;"
        : "=l"(*reinterpret_cast<unsigned long long*>(&d))
        : "l"(*reinterpret_cast<unsigned long long*>(&a)),
          "l"(*reinterpret_cast<unsigned long long*>(&b)),
          "l"(*reinterpret_cast<unsigned long long*>(&c)));
    return d;
}

__device__ __forceinline__ void cp16(void* smem_dst, const void* gmem_src) {
    unsigned sdst = (unsigned)__cvta_generic_to_shared(smem_dst);
    asm volatile("cp.async.cg.shared.global [%0], [%1], 16;"
                 :: "r"(sdst), "l"(gmem_src) : "memory");
}
__device__ __forceinline__ void cp_commit() {
    asm volatile("cp.async.commit_group;" ::: "memory");
}
__device__ __forceinline__ void cp_wait0() {
    asm volatile("cp.async.wait_group 0;" ::: "memory");
}

// =======================================================================
// kernel 1: [16384 x 1024] @ [1024 x 33] projection (wc | we | sum_be)
//   BM=128, thread tile m=4 x n=5. A pitch 34 (2-way max conflicts),
//   A staged via LDG reg-prefetch + STS.32; W via cp.async double buffer.
// =======================================================================
#define K1_BM 128
#define K1_KC 32
#define PA 34          // A pitch in floats: lane bank stride 2 -> <=2-way
#define PW 36          // W pitch (uniform reads; 16B-aligned rows for cp.async)
#define NCHUNK (HN / K1_KC)

__global__ __launch_bounds__(256, 1)
void k1_proj(const float* __restrict__ hs,
             const float* __restrict__ wc,
             const float* __restrict__ bc,
             const float* __restrict__ we,
             const float* __restrict__ be,
             const float* __restrict__ strength) {
    __shared__ float besum_s[HN];
    __shared__ __align__(16) float As[2][K1_BM * PA];
    __shared__ __align__(16) float Ws[2][40 * PW];

    const int tid = threadIdx.x;
    const int x = tid & 31;          // row lane
    const int y = tid >> 5;          // n-group (0..7), 5 outputs each
    const int rowBase = blockIdx.x * K1_BM;

    // zero Ws (rows 33-39 stay zero)
    for (int i = tid; i < 2 * 40 * PW; i += 256)
        (&Ws[0][0])[i] = 0.f;

    // per-CTA redundant besum (4 cols per thread, coalesced)
    #pragma unroll
    for (int j = 0; j < 4; j++) {
        int col = tid + 256 * j;
        float s = 0.f;
        #pragma unroll
        for (int r = 0; r < RN; r++) s += be[r * HN + col];
        besum_s[col] = s;
    }

    // A-prefetch addressing: thread i covers (row = idx>>3, k4 = idx&7)
    const int arow0 = tid >> 3;          // rows arow0, +32, +64, +96
    const int ak4 = tid & 7;

    auto ldgA = [&](int c, float4* pref) {
        #pragma unroll
        for (int i = 0; i < 4; i++)
            pref[i] = *reinterpret_cast<const float4*>(
                &hs[(size_t)(rowBase + arow0 + 32 * i) * HN + c * K1_KC + ak4 * 4]);
    };
    auto stsA = [&](int buf, const float4* pref) {
        #pragma unroll
        for (int i = 0; i < 4; i++) {
            float* dst = &As[buf][(arow0 + 32 * i) * PA + ak4 * 4];
            dst[0] = pref[i].x; dst[1] = pref[i].y;
            dst[2] = pref[i].z; dst[3] = pref[i].w;
        }
    };
    auto stageW = [&](int c, int buf) {
        int n = tid >> 3, k4 = tid & 7;
        const float* src = (n < 16)
            ? &wc[n * HN + c * K1_KC + k4 * 4]
            : &we[(n - 16) * HN + c * K1_KC + k4 * 4];
        cp16(&Ws[buf][n * PW + k4 * 4], src);
        cp_commit();
        if (tid < 32)
            Ws[buf][32 * PW + tid] = besum_s[c * K1_KC + tid];
    };

    float2 acc[4][5];
    #pragma unroll
    for (int m = 0; m < 4; m++)
        #pragma unroll
        for (int nn = 0; nn < 5; nn++) acc[m][nn] = make_float2(0.f, 0.f);

    float4 pref[4];
    ldgA(0, pref);
    __syncthreads();          // besum_s ready before stageW reads it
    stageW(0, 0);

    for (int c = 0; c < NCHUNK; c++) {
        const int buf = c & 1;
        stsA(buf, pref);
        cp_wait0();
        __syncthreads();
        if (c + 1 < NCHUNK) {
            ldgA(c + 1, pref);
            stageW(c + 1, 1 - buf);
        }

        #pragma unroll
        for (int kp = 0; kp < K1_KC / 2; kp++) {
            float2 a2[4], b2[5];
            #pragma unroll
            for (int m = 0; m < 4; m++)
                a2[m] = *reinterpret_cast<const float2*>(
                    &As[buf][(x + 32 * m) * PA + 2 * kp]);
            #pragma unroll
            for (int nn = 0; nn < 5; nn++)
                b2[nn] = *reinterpret_cast<const float2*>(
                    &Ws[buf][(y * 5 + nn) * PW + 2 * kp]);
            #pragma unroll
            for (int m = 0; m < 4; m++)
                #pragma unroll
                for (int nn = 0; nn < 5; nn++)
                    acc[m][nn] = ffma2(a2[m], b2[nn], acc[m][nn]);
        }
        __syncthreads();
    }

    // epilogue
    #pragma unroll
    for (int m = 0; m < 4; m++) {
        int row = rowBase + x + 32 * m;
        int b = row >> 12;
        int s = row & (SN - 1);
        #pragma unroll
        for (int nn = 0; nn < 5; nn++) {
            int n = y * 5 + nn;
            float val = acc[m][nn].x + acc[m][nn].y;
            if (n < 16) {
                float p = (val + bc[n]) * strength[n];
                g_Pd[(b * SN + s) * RN + n] = make_float2(p, p);
            } else if (n < 32) {
                g_Ut[(b * RN + (n - 16)) * SN + s] = val;
            } else if (n == 32) {
                g_V[b * SN + s] = val;
            }
        }
    }
}

// =======================================================================
// kernel 2: bias[b,s,t] = sum_r P[b,s,r]*U[b,r,t] + V[b,t]
//   (unchanged from R4 — at the DRAM-store wall)
// =======================================================================
#define K2_TB 1024
#define K2_SB 64

__global__ __launch_bounds__(256, 2)
void k2_outer(float* __restrict__ out) {
    __shared__ __align__(16) float4 Ps[K2_SB * 8];   // 8KB

    const int tid = threadIdx.x;
    const int w = tid >> 5;
    const int l = tid & 31;
    const int b = blockIdx.z;
    const int sB = blockIdx.y * K2_SB;
    const int t = blockIdx.x * K2_TB + w * 128 + l * 4;

    const float4* psrc = reinterpret_cast<const float4*>(&g_Pd[(b * SN + sB) * RN]);
    Ps[tid] = psrc[tid];
    Ps[tid + 256] = psrc[tid + 256];

    float4 u[RN];
    #pragma unroll
    for (int r = 0; r < RN; r++)
        u[r] = *reinterpret_cast<const float4*>(&g_Ut[(b * RN + r) * SN + t]);

    float4 vv = *reinterpret_cast<const float4*>(&g_V[b * SN + t]);
    const float2 va = make_float2(vv.x, vv.y);
    const float2 vb = make_float2(vv.z, vv.w);

    __syncthreads();

    float* orow = out + (size_t)(b * SN + sB) * SN + t;

    #pragma unroll 2
    for (int si = 0; si < K2_SB; si++) {
        float4 pq[8];
        #pragma unroll
        for (int j = 0; j < 8; j++) pq[j] = Ps[si * 8 + j];

        float2 a = va, c2 = vb;
        #pragma unroll
        for (int r = 0; r < RN; r++) {
            float2 p = (r & 1) ? make_float2(pq[r >> 1].z, pq[r >> 1].w)
                               : make_float2(pq[r >> 1].x, pq[r >> 1].y);
            a  = ffma2(p, make_float2(u[r].x, u[r].y), a);
            c2 = ffma2(p, make_float2(u[r].z, u[r].w), c2);
        }

        *reinterpret_cast<float4*>(orow + (size_t)si * SN) =
            make_float4(a.x, a.y, c2.x, c2.y);
    }
}

// ---------------- launch ----------------
extern "C" void kernel_launch(void* const* d_in, const int* in_sizes, int n_in,
                              void* d_out, int out_size) {
    const float* hs       = (const float*)d_in[0];
    const float* wc       = (const float*)d_in[1];
    const float* bc       = (const float*)d_in[2];
    const float* we       = (const float*)d_in[3];
    const float* be       = (const float*)d_in[4];
    const float* strength = (const float*)d_in[5];
    float* out = (float*)d_out;

    k1_proj<<<(BN * SN) / K1_BM, 256>>>(hs, wc, bc, we, be, strength);
    k2_outer<<<dim3(SN / K2_TB, SN / K2_SB, BN), 256>>>(out);
}

// round 6
// speedup vs baseline: 2.4689x; 1.0233x over previous
#include <cuda_runtime.h>

// Problem constants
#define SN 4096
#define HN 1024
#define BN 4
#define RN 16
#define ROWS_TOT (BN * SN)     // 16384

// ---------------- scratch (device globals; no allocation) ----------------
__device__ float  g_part[2 * 33 * ROWS_TOT];  // split-K partials [kh][j][row]
__device__ float2 g_Pd[BN * SN * RN];         // scaled cause scores {p,p} [b][s][r]
__device__ float  g_Ut[BN * RN * SN];         // effect dot [b][r][t]
__device__ float  g_V[BN * SN];               // bias-term dot [b][t]

// packed f32x2 FMA (SASS FFMA2)
__device__ __forceinline__ float2 ffma2(float2 a, float2 b, float2 c) {
    float2 d;
    asm("fma.rn.f32x2 %0, %1, %2, %3;"
        : "=l"(*reinterpret_cast<unsigned long long*>(&d))
        : "l"(*reinterpret_cast<unsigned long long*>(&a)),
          "l"(*reinterpret_cast<unsigned long long*>(&b)),
          "l"(*reinterpret_cast<unsigned long long*>(&c)));
    return d;
}

__device__ __forceinline__ void cp16(void* smem_dst, const void* gmem_src) {
    unsigned sdst = (unsigned)__cvta_generic_to_shared(smem_dst);
    asm volatile("cp.async.cg.shared.global [%0], [%1], 16;"
                 :: "r"(sdst), "l"(gmem_src) : "memory");
}
__device__ __forceinline__ void cp_commit() {
    asm volatile("cp.async.commit_group;" ::: "memory");
}
__device__ __forceinline__ void cp_wait0() {
    asm volatile("cp.async.wait_group 0;" ::: "memory");
}

// =======================================================================
// kernel 1: split-K projection partials.
//   grid (128, 2): x = 128-row block, y = k-half. 256 thr, occ 2.
//   Warp = (rh, g): rows x+32*rh (+64), n = g*8..g*8+7 of [wc|we].
//   Per 2-kp: 2 LDS.128 (a, conflict-free @pitch36) + 8 uniform LDS.128 (b)
//   + 32 FFMA2. g==0 warps also accumulate V against besum slice.
// =======================================================================
#define K1_BM 128
#define KC 32
#define PT 36          // pitch (floats): 16B rows, quarter-warp conflict-free
#define KHALF 512
#define NCH (KHALF / KC)   // 16 chunks per CTA

__global__ __launch_bounds__(256, 2)
void k1_proj(const float* __restrict__ hs,
             const float* __restrict__ wc,
             const float* __restrict__ we,
             const float* __restrict__ be) {
    __shared__ float besum_s[KHALF];
    __shared__ __align__(16) float As[2][K1_BM * PT];
    __shared__ __align__(16) float Ws[2][32 * PT];

    const int tid = threadIdx.x;
    const int x = tid & 31;
    const int wid = tid >> 5;
    const int rh = wid & 1;
    const int g = wid >> 1;          // n-group 0..3
    const int rowBase = blockIdx.x * K1_BM;
    const int kh = blockIdx.y;
    const int kOff = kh * KHALF;

    // besum slice for this k-half (2 cols per thread, coalesced per rule)
    #pragma unroll
    for (int j = 0; j < 2; j++) {
        int col = tid + 256 * j;
        float s = 0.f;
        #pragma unroll
        for (int r = 0; r < RN; r++) s += be[r * HN + kOff + col];
        besum_s[col] = s;
    }

    auto stage = [&](int c, int buf) {
        // A: 128 rows x 32 k = 1024 float4, 4 per thread
        #pragma unroll
        for (int i = 0; i < 4; i++) {
            int idx = tid + 256 * i;
            int row = idx >> 3, k4 = idx & 7;
            cp16(&As[buf][row * PT + k4 * 4],
                 &hs[(size_t)(rowBase + row) * HN + kOff + c * KC + k4 * 4]);
        }
        // W: 32 n x 32 k = 256 float4, 1 per thread
        {
            int n = tid >> 3, k4 = tid & 7;
            const float* src = (n < 16)
                ? &wc[n * HN + kOff + c * KC + k4 * 4]
                : &we[(n - 16) * HN + kOff + c * KC + k4 * 4];
            cp16(&Ws[buf][n * PT + k4 * 4], src);
        }
        cp_commit();
    };

    float2 acc[2][8];
    #pragma unroll
    for (int m = 0; m < 2; m++)
        #pragma unroll
        for (int n = 0; n < 8; n++) acc[m][n] = make_float2(0.f, 0.f);
    float2 vacc[2] = {make_float2(0.f, 0.f), make_float2(0.f, 0.f)};

    stage(0, 0);

    const int r0 = x + 32 * rh;          // row 0 offset in tile (row1 = +64)

    for (int c = 0; c < NCH; c++) {
        cp_wait0();
        __syncthreads();
        if (c + 1 < NCH) stage(c + 1, (c + 1) & 1);
        const int buf = c & 1;

        #pragma unroll
        for (int q = 0; q < 8; q++) {            // 4 k per q
            float4 a0 = *reinterpret_cast<const float4*>(&As[buf][r0 * PT + 4 * q]);
            float4 a1 = *reinterpret_cast<const float4*>(&As[buf][(r0 + 64) * PT + 4 * q]);
            float2 a0lo = make_float2(a0.x, a0.y), a0hi = make_float2(a0.z, a0.w);
            float2 a1lo = make_float2(a1.x, a1.y), a1hi = make_float2(a1.z, a1.w);
            #pragma unroll
            for (int n = 0; n < 8; n++) {
                float4 w4 = *reinterpret_cast<const float4*>(
                    &Ws[buf][(g * 8 + n) * PT + 4 * q]);     // uniform LDS.128
                acc[0][n] = ffma2(a0lo, make_float2(w4.x, w4.y), acc[0][n]);
                acc[0][n] = ffma2(a0hi, make_float2(w4.z, w4.w), acc[0][n]);
                acc[1][n] = ffma2(a1lo, make_float2(w4.x, w4.y), acc[1][n]);
                acc[1][n] = ffma2(a1hi, make_float2(w4.z, w4.w), acc[1][n]);
            }
            if (g == 0) {   // besum -> V partial (warp-uniform branch)
                float4 b4 = *reinterpret_cast<const float4*>(&besum_s[c * KC + 4 * q]);
                vacc[0] = ffma2(a0lo, make_float2(b4.x, b4.y), vacc[0]);
                vacc[0] = ffma2(a0hi, make_float2(b4.z, b4.w), vacc[0]);
                vacc[1] = ffma2(a1lo, make_float2(b4.x, b4.y), vacc[1]);
                vacc[1] = ffma2(a1hi, make_float2(b4.z, b4.w), vacc[1]);
            }
        }
        __syncthreads();
    }

    // write partials
    #pragma unroll
    for (int m = 0; m < 2; m++) {
        int row = rowBase + r0 + 64 * m;
        #pragma unroll
        for (int n = 0; n < 8; n++) {
            int j = g * 8 + n;
            g_part[(kh * 33 + j) * ROWS_TOT + row] = acc[m][n].x + acc[m][n].y;
        }
        if (g == 0)
            g_part[(kh * 33 + 32) * ROWS_TOT + row] = vacc[m].x + vacc[m].y;
    }
}

// =======================================================================
// k1_reduce: sum the 2 k-half partials, apply epilogue, scatter.
// =======================================================================
__global__ __launch_bounds__(256)
void k1_reduce(const float* __restrict__ bc,
               const float* __restrict__ strength) {
    const int row = blockIdx.x * 256 + threadIdx.x;
    const int j = blockIdx.y;
    float v = g_part[j * ROWS_TOT + row] +
              g_part[(33 + j) * ROWS_TOT + row];
    const int b = row >> 12;
    const int s = row & (SN - 1);
    if (j < 16) {
        float p = (v + bc[j]) * strength[j];
        g_Pd[(b * SN + s) * RN + j] = make_float2(p, p);
    } else if (j < 32) {
        g_Ut[(b * RN + (j - 16)) * SN + s] = v;
    } else {
        g_V[b * SN + s] = v;
    }
}

// =======================================================================
// kernel 2: bias[b,s,t] = sum_r P[b,s,r]*U[b,r,t] + V[b,t]  (unchanged)
// =======================================================================
#define K2_TB 1024
#define K2_SB 64

__global__ __launch_bounds__(256, 2)
void k2_outer(float* __restrict__ out) {
    __shared__ __align__(16) float4 Ps[K2_SB * 8];   // 8KB

    const int tid = threadIdx.x;
    const int w = tid >> 5;
    const int l = tid & 31;
    const int b = blockIdx.z;
    const int sB = blockIdx.y * K2_SB;
    const int t = blockIdx.x * K2_TB + w * 128 + l * 4;

    const float4* psrc = reinterpret_cast<const float4*>(&g_Pd[(b * SN + sB) * RN]);
    Ps[tid] = psrc[tid];
    Ps[tid + 256] = psrc[tid + 256];

    float4 u[RN];
    #pragma unroll
    for (int r = 0; r < RN; r++)
        u[r] = *reinterpret_cast<const float4*>(&g_Ut[(b * RN + r) * SN + t]);

    float4 vv = *reinterpret_cast<const float4*>(&g_V[b * SN + t]);
    const float2 va = make_float2(vv.x, vv.y);
    const float2 vb = make_float2(vv.z, vv.w);

    __syncthreads();

    float* orow = out + (size_t)(b * SN + sB) * SN + t;

    #pragma unroll 2
    for (int si = 0; si < K2_SB; si++) {
        float4 pq[8];
        #pragma unroll
        for (int j = 0; j < 8; j++) pq[j] = Ps[si * 8 + j];

        float2 a = va, c2 = vb;
        #pragma unroll
        for (int r = 0; r < RN; r++) {
            float2 p = (r & 1) ? make_float2(pq[r >> 1].z, pq[r >> 1].w)
                               : make_float2(pq[r >> 1].x, pq[r >> 1].y);
            a  = ffma2(p, make_float2(u[r].x, u[r].y), a);
            c2 = ffma2(p, make_float2(u[r].z, u[r].w), c2);
        }

        *reinterpret_cast<float4*>(orow + (size_t)si * SN) =
            make_float4(a.x, a.y, c2.x, c2.y);
    }
}

// ---------------- launch ----------------
extern "C" void kernel_launch(void* const* d_in, const int* in_sizes, int n_in,
                              void* d_out, int out_size) {
    const float* hs       = (const float*)d_in[0];
    const float* wc       = (const float*)d_in[1];
    const float* bc       = (const float*)d_in[2];
    const float* we       = (const float*)d_in[3];
    const float* be       = (const float*)d_in[4];
    const float* strength = (const float*)d_in[5];
    float* out = (float*)d_out;

    k1_proj<<<dim3(ROWS_TOT / K1_BM, 2), 256>>>(hs, wc, we, be);
    k1_reduce<<<dim3(ROWS_TOT / 256, 33), 256>>>(bc, strength);
    k2_outer<<<dim3(SN / K2_TB, SN / K2_SB, BN), 256>>>(out);
}